// round 1
// baseline (speedup 1.0000x reference)
#include <cuda_runtime.h>

#define T_LEN 32768
#define C_LEN 16
#define B_LEN 64
#define NROWS (B_LEN * C_LEN)   // 1024 rows of length T
#define NTHREADS 1024
#define ITEMS (T_LEN / NTHREADS) // 32 items per thread
#define SMEM_FLOATS (T_LEN + (T_LEN >> 5))  // padded: 33792 floats = 135168 B

__device__ float g_partial[NROWS];

__device__ __forceinline__ int padidx(int i) { return i + (i >> 5); }

__global__ void __launch_bounds__(NTHREADS, 1)
wass_row_kernel(const float* __restrict__ yp, const float* __restrict__ yt) {
    extern __shared__ float s[];              // padded diff buffer
    __shared__ float warp_scr[32];

    const int tid  = threadIdx.x;
    const int lane = tid & 31;
    const int wid  = tid >> 5;

    const long base = (long)blockIdx.x * T_LEN;
    const float4* __restrict__ p4 = (const float4*)(yp + base);
    const float4* __restrict__ t4 = (const float4*)(yt + base);

    // Phase 1: coalesced vectorized load, stage diff into padded smem.
    // For a float4 at element i = 4v, all 4 elements share (i>>5), so one pad offset.
    #pragma unroll
    for (int v = tid; v < T_LEN / 4; v += NTHREADS) {
        float4 a = p4[v];
        float4 b = t4[v];
        int i = v * 4;
        int o = i + (i >> 5);
        s[o + 0] = a.x - b.x;
        s[o + 1] = a.y - b.y;
        s[o + 2] = a.z - b.z;
        s[o + 3] = a.w - b.w;
    }
    __syncthreads();

    // Phase 2: per-thread contiguous segment sum.
    // padidx(tid*32 + k) = tid*33 + k  -> stride 33 across threads: conflict-free.
    const int segbase = tid * ITEMS;
    const int sb = padidx(segbase);
    float seg = 0.0f;
    #pragma unroll
    for (int k = 0; k < ITEMS; k++) seg += s[sb + k];

    // Warp inclusive scan of segment sums.
    float inc = seg;
    #pragma unroll
    for (int d = 1; d < 32; d <<= 1) {
        float y = __shfl_up_sync(0xffffffffu, inc, d);
        if (lane >= d) inc += y;
    }
    if (lane == 31) warp_scr[wid] = inc;
    __syncthreads();
    if (wid == 0) {
        float wv = warp_scr[lane];
        float winc = wv;
        #pragma unroll
        for (int d = 1; d < 32; d <<= 1) {
            float y = __shfl_up_sync(0xffffffffu, winc, d);
            if (lane >= d) winc += y;
        }
        warp_scr[lane] = winc - wv;   // exclusive scan of warp totals
    }
    __syncthreads();
    const float carry = warp_scr[wid] + (inc - seg);  // exclusive prefix for this thread

    // Phase 3: serial running cumsum within segment, weighted abs accumulation.
    float acc = 0.0f;
    float run = carry;
    #pragma unroll
    for (int k = 0; k < ITEMS; k++) {
        run += s[sb + k];
        float w = (float)(T_LEN - (segbase + k));   // weight T - t, t 0-indexed
        acc = fmaf(fabsf(run), w, acc);
    }

    // Deterministic block reduction of acc.
    #pragma unroll
    for (int d = 16; d > 0; d >>= 1) acc += __shfl_down_sync(0xffffffffu, acc, d);
    __syncthreads();                                  // protect warp_scr reuse
    if (lane == 0) warp_scr[wid] = acc;
    __syncthreads();
    if (wid == 0) {
        float v = warp_scr[lane];
        #pragma unroll
        for (int d = 16; d > 0; d >>= 1) v += __shfl_down_sync(0xffffffffu, v, d);
        if (lane == 0) g_partial[blockIdx.x] = v;
    }
}

__global__ void __launch_bounds__(NROWS)
wass_reduce_kernel(float* __restrict__ out) {
    __shared__ double scr[32];
    const int tid  = threadIdx.x;
    const int lane = tid & 31;
    const int wid  = tid >> 5;

    double v = (double)g_partial[tid];
    #pragma unroll
    for (int d = 16; d > 0; d >>= 1) v += __shfl_down_sync(0xffffffffu, v, d);
    if (lane == 0) scr[wid] = v;
    __syncthreads();
    if (wid == 0) {
        double x = scr[lane];
        #pragma unroll
        for (int d = 16; d > 0; d >>= 1) x += __shfl_down_sync(0xffffffffu, x, d);
        if (lane == 0) {
            double tc = (double)T_LEN * (double)C_LEN;          // T*C
            double scale = 2.0 / (tc * (tc + 1.0));
            out[0] = (float)((x / (double)B_LEN) * scale);
        }
    }
}

extern "C" void kernel_launch(void* const* d_in, const int* in_sizes, int n_in,
                              void* d_out, int out_size) {
    (void)in_sizes; (void)n_in; (void)out_size;
    const float* y_pred = (const float*)d_in[0];
    const float* y_true = (const float*)d_in[1];
    float* out = (float*)d_out;

    const int smem_bytes = SMEM_FLOATS * (int)sizeof(float);  // 135168 B
    cudaFuncSetAttribute(wass_row_kernel,
                         cudaFuncAttributeMaxDynamicSharedMemorySize, smem_bytes);

    wass_row_kernel<<<NROWS, NTHREADS, smem_bytes>>>(y_pred, y_true);
    wass_reduce_kernel<<<1, NROWS>>>(out);
}